// round 3
// baseline (speedup 1.0000x reference)
#include <cuda_runtime.h>
#include <cuda_bf16.h>
#include <cstdint>

#define Bsz 64
#define Ssz 256
#define Isz 128
#define Hsz 128
#define UNF 6

#define SEQ_TPB 256
#define HHALF 64
#define RABSTR 68   // float2 per rab row (bank-stagger: 136 words ≡ 8 mod 32)
#define PWSTR  72   // floats per pw/sa row (72 ≡ 8 mod 32)

// ---------------- device scratch ----------------
__device__ float2 g_rab[Hsz*Hsz];       // (a,b): a=0.5*sigma, b=-0.5*sigma*mu, [src][dst]
__device__ float  g_rcs[Hsz*Hsz];       // 0.5*softplus(w)*erev, [src][dst]
__device__ float2 g_sab[Isz*Hsz];
__device__ float  g_scs[Isz*Hsz];
__device__ float  g_numconst[Hsz];
__device__ float  g_denconst[Hsz];
__device__ float  g_cmt[Hsz];
__device__ float  g_pwF[Hsz*Hsz];       // phase_W transposed [k][h]
__device__ float  g_saF[Hsz*Hsz];       // sa_W transposed [k][h]
__device__ float  g_numbase[Bsz*Ssz*Hsz];
__device__ float  g_denbase[Bsz*Ssz*Hsz];

// ---------------- helpers ----------------
__device__ __forceinline__ float sp(float x) { return log1pf(expf(x)); }
__device__ __forceinline__ float tanhap(float x) {
    float y; asm("tanh.approx.f32 %0, %1;" : "=f"(y) : "f"(x)); return y;
}
__device__ __forceinline__ float fabsb(float x) {
    return __int_as_float(__float_as_int(x) & 0x7fffffff);
}
__device__ __forceinline__ uint32_t smem_u32(const void* p) {
    uint32_t a; asm("{ .reg .u64 t; cvta.to.shared.u64 t, %1; cvt.u32.u64 %0, t; }" : "=r"(a) : "l"(p));
    return a;
}
__device__ __forceinline__ void mbar_init(uint32_t mbar, uint32_t cnt) {
    asm volatile("mbarrier.init.shared.b64 [%0], %1;" :: "r"(mbar), "r"(cnt) : "memory");
}
__device__ __forceinline__ void mbar_wait_cluster(uint32_t mbar, uint32_t par) {
    asm volatile(
        "{\n\t.reg .pred P;\n"
        "WL_%=:\n\t"
        "mbarrier.try_wait.parity.acquire.cluster.shared::cta.b64 P, [%0], %1, 0x989680;\n\t"
        "@!P bra WL_%=;\n\t}"
        :: "r"(mbar), "r"(par) : "memory");
}
__device__ __forceinline__ void st_remote_f32(uint32_t addr, float v) {
    asm volatile("st.shared::cluster.f32 [%0], %1;" :: "r"(addr), "f"(v) : "memory");
}
__device__ __forceinline__ void arrive_remote(uint32_t mbar) {
    asm volatile("mbarrier.arrive.release.cluster.shared::cluster.b64 _, [%0];" :: "r"(mbar) : "memory");
}

// ---------------- kernel A: per-edge param folding ----------------
__global__ void prep_kernel(const float* __restrict__ sigma, const float* __restrict__ mu,
                            const float* __restrict__ w,     const float* __restrict__ erev,
                            const float* __restrict__ s_sigma, const float* __restrict__ s_mu,
                            const float* __restrict__ s_w,   const float* __restrict__ s_erev,
                            const float* __restrict__ input_w, const float* __restrict__ input_b)
{
    int r = blockIdx.x, h = threadIdx.x;
    if (r < Hsz) {
        int idx = r*Hsz + h;
        float a = 0.5f * sigma[idx];
        g_rab[idx] = make_float2(a, -a * mu[idx]);
        g_rcs[idx] = 0.5f * sp(w[idx]) * erev[idx];
    } else {
        int i = r - Hsz;
        int idx = i*Hsz + h;
        float a = 0.5f * s_sigma[idx];
        g_sab[idx] = make_float2(a * input_w[i], a * (input_b[i] - s_mu[idx]));
        g_scs[idx] = 0.5f * sp(s_w[idx]) * s_erev[idx];
    }
}

// ---------------- kernel A2: per-h constants + transposed fp32 matmul weights ----------------
__global__ void prep2_kernel(const float* __restrict__ gleak, const float* __restrict__ vleak,
                             const float* __restrict__ cm,
                             const float* __restrict__ phase_W, const float* __restrict__ sa_W)
{
    int h = threadIdx.x;
    float nc = 0.f, dc = 0.f;
    for (int j = 0; j < Hsz; j++) { float cs = g_rcs[j*Hsz + h]; nc += cs; dc += fabsf(cs); }
    for (int i = 0; i < Isz; i++) { float cs = g_scs[i*Hsz + h]; nc += cs; dc += fabsf(cs); }
    float gl  = sp(gleak[h]);
    float cmt = sp(cm[h]) * (float)UNF;
    g_numconst[h] = gl * vleak[h] + nc;
    g_denconst[h] = cmt + gl + 1e-8f + dc;
    g_cmt[h] = cmt;
    for (int k = 0; k < Hsz; k++) {
        g_pwF[k*Hsz + h] = phase_W[h*Hsz + k];
        g_saF[k*Hsz + h] = sa_W[h*Hsz + k];
    }
}

// ---------------- kernel B: sensory pre-pass (unchanged from R2) ----------------
__global__ __launch_bounds__(512, 1) void sens_kernel(const float* __restrict__ x)
{
    extern __shared__ float sm[];
    float2* sab = (float2*)sm;
    float*  xs  = sm + 2*Isz*Hsz;
    float*  pn  = xs + 128;
    float*  pd  = pn + 512;

    int tid = threadIdx.x;
    int h = tid & 127, g = tid >> 7;

    for (int r = tid; r < Isz*Hsz; r += 512) sab[r] = g_sab[r];

    float scs[32];
    #pragma unroll
    for (int il = 0; il < 32; il++) scs[il] = g_scs[(g*32 + il)*Hsz + h];

    float ncst = g_numconst[h], dcst = g_denconst[h];
    int s = blockIdx.x;

    for (int bb = 0; bb < 16; bb++) {
        int b = blockIdx.y * 16 + bb;
        __syncthreads();
        if (tid < Isz) xs[h] = x[(b*Ssz + s)*Isz + h];
        __syncthreads();
        float n = 0.f, d = 0.f;
        #pragma unroll
        for (int q = 0; q < 8; q++) {
            float4 x4 = *(const float4*)(xs + g*32 + 4*q);
            float xv[4] = {x4.x, x4.y, x4.z, x4.w};
            #pragma unroll
            for (int e = 0; e < 4; e++) {
                int il = 4*q + e;
                float2 p = sab[(g*32 + il)*Hsz + h];
                float t = tanhap(fmaf(p.x, xv[e], p.y));
                n = fmaf(scs[il], t, n);
                d = fmaf(fabsb(scs[il]), t, d);
            }
        }
        pn[g*Hsz + h] = n; pd[g*Hsz + h] = d;
        __syncthreads();
        if (g == 0) {
            float num = ncst + pn[h] + pn[Hsz + h] + pn[2*Hsz + h] + pn[3*Hsz + h];
            float den = dcst + pd[h] + pd[Hsz + h] + pd[2*Hsz + h] + pd[3*Hsz + h];
            int o = (b*Ssz + s)*Hsz + h;
            g_numbase[o] = num;
            g_denbase[o] = den;
        }
    }
}

// ---------------- smem byte offsets for seq kernel ----------------
#define OFF_RAB   0
#define OFF_PWF   69632              // 128*68*8
#define OFF_SAF   106496             // +128*72*4
#define OFF_VOWN  143360             // +128*72*4
#define OFF_VPEER 143872             // +2*64*4
#define OFF_SGOWN 144384             // +2*64*4
#define OFF_SGPEER 144640            // +64*4
#define OFF_MBAR  145152             // +2*64*4
#define SMEM_SEQ  145408

// ---------------- kernel C: sequential scan, 2-CTA cluster per batch ----------------
__global__ __launch_bounds__(SEQ_TPB, 1) __cluster_dims__(2, 1, 1)
void seq_kernel(const float* __restrict__ h0, const float* __restrict__ amplitude,
                const float* __restrict__ omega, const float* __restrict__ phase_b,
                const float* __restrict__ alpha_p, const float* __restrict__ beta_p,
                float* __restrict__ out, int write_hfinal)
{
    extern __shared__ char smc[];
    float2* rab   = (float2*)(smc + OFF_RAB);     // [128][RABSTR] cols = own 64 h
    float*  pwf   = (float*) (smc + OFF_PWF);     // [128][PWSTR]
    float*  saf   = (float*) (smc + OFF_SAF);     // [128][PWSTR]
    float*  vown  = (float*) (smc + OFF_VOWN);    // [2][64]
    float*  vpeer = (float*) (smc + OFF_VPEER);   // [2][64]
    float*  sgown = (float*) (smc + OFF_SGOWN);   // [64]
    float*  sgpeer= (float*) (smc + OFF_SGPEER);  // [2][64]

    uint32_t sbase = smem_u32(smc);
    uint32_t mbar  = sbase + OFF_MBAR;

    uint32_t rank; asm("mov.u32 %0, %%cluster_ctarank;" : "=r"(rank));
    uint32_t peerR = rank ^ 1u;
    int b = blockIdx.x >> 1;
    int own_base  = (int)rank * HHALF;
    int peer_base = (int)peerR * HHALF;

    int tid  = threadIdx.x;
    int lane = tid & 31;
    int warp = tid >> 5;
    int g    = lane & 3;
    int hl   = (warp << 3) | (lane >> 2);       // 0..63 local dst
    int habs = own_base + hl;

    // preload smem (own dst half columns of all matrices)
    for (int idx = tid; idx < Hsz*HHALF; idx += SEQ_TPB) {
        int j = idx >> 6, c = idx & 63;
        rab[j*RABSTR + c] = g_rab[j*Hsz + own_base + c];
        pwf[j*PWSTR  + c] = g_pwF[j*Hsz + own_base + c];
        saf[j*PWSTR  + c] = g_saF[j*Hsz + own_base + c];
    }

    // per-thread edge weights: srcs j = base + jl*4 + g
    float cso[16], csp[16];
    #pragma unroll
    for (int jl = 0; jl < 16; jl++) {
        cso[jl] = g_rcs[(own_base  + jl*4 + g)*Hsz + habs];
        csp[jl] = g_rcs[(peer_base + jl*4 + g)*Hsz + habs];
    }
    float cmt = g_cmt[habs];
    float aa  = alpha_p[0] * amplitude[habs];
    float om  = omega[habs];
    float pb  = phase_b[habs];
    float bet = beta_p[0];

    if (tid == 0) mbar_init(mbar, 64);
    __syncthreads();
    asm volatile("barrier.cluster.arrive.aligned;" ::: "memory");
    asm volatile("barrier.cluster.wait.aligned;"   ::: "memory");

    uint32_t vpeer_rm, sgpeer_rm, mbar_rm;
    asm("mapa.shared::cluster.u32 %0, %1, %2;" : "=r"(vpeer_rm)  : "r"(sbase + OFF_VPEER),  "r"(peerR));
    asm("mapa.shared::cluster.u32 %0, %1, %2;" : "=r"(sgpeer_rm) : "r"(sbase + OFF_SGPEER), "r"(peerR));
    asm("mapa.shared::cluster.u32 %0, %1, %2;" : "=r"(mbar_rm)   : "r"(sbase + OFF_MBAR),   "r"(peerR));

    float v = h0[b*Hsz + habs];
    int vb = 0;           // last-written vown buffer
    uint32_t sc = 0, rc = 0;

    // init exchange: publish h0 own half (send #0)
    if (g == 0) {
        vown[vb*HHALF + hl] = v;
        st_remote_f32(vpeer_rm + ((sc & 1u)*HHALF + hl)*4u, v);
        arrive_remote(mbar_rm);
    }
    sc++;
    __syncthreads();

    float nb = g_numbase[(b*Ssz)*Hsz + habs];
    float db = g_denbase[(b*Ssz)*Hsz + habs];

    for (int s = 0; s < Ssz; s++) {
        float nb_n = 0.f, db_n = 0.f;
        if (s + 1 < Ssz) {
            nb_n = g_numbase[(b*Ssz + s + 1)*Hsz + habs];
            db_n = g_denbase[(b*Ssz + s + 1)*Hsz + habs];
        }

        #pragma unroll 1
        for (int u = 0; u < UNF; u++) {
            float n = 0.f, d = 0.f;
            // own-half srcs (local data — overlaps peer's in-flight write)
            const float* vo = vown + vb*HHALF;
            #pragma unroll
            for (int jl = 0; jl < 16; jl++) {
                int jp = jl*4 + g;
                float vv = vo[jp];
                float2 p = rab[(own_base + jp)*RABSTR + hl];
                float t = tanhap(fmaf(p.x, vv, p.y));
                n = fmaf(cso[jl], t, n);
                d = fmaf(fabsb(cso[jl]), t, d);
            }
            // receive peer half of v
            int buf = rc & 1;
            mbar_wait_cluster(mbar, rc & 1u); rc++;
            const float* vp = vpeer + buf*HHALF;
            #pragma unroll
            for (int jl = 0; jl < 16; jl++) {
                int jp = jl*4 + g;
                float vv = vp[jp];
                float2 p = rab[(peer_base + jp)*RABSTR + hl];
                float t = tanhap(fmaf(p.x, vv, p.y));
                n = fmaf(csp[jl], t, n);
                d = fmaf(fabsb(csp[jl]), t, d);
            }
            n += __shfl_xor_sync(0xffffffffu, n, 1);
            n += __shfl_xor_sync(0xffffffffu, n, 2);
            d += __shfl_xor_sync(0xffffffffu, d, 1);
            d += __shfl_xor_sync(0xffffffffu, d, 2);
            v = __fdividef(fmaf(cmt, v, nb + n), db + d);
            vb ^= 1;
            if (g == 0) {
                vown[vb*HHALF + hl] = v;
                st_remote_f32(vpeer_rm + ((sc & 1u)*HHALF + hl)*4u, v);
                arrive_remote(mbar_rm);
            }
            sc++;
            __syncthreads();
        }

        // ---- pulse: phi = v @ phase_W.T + phase_b ----
        float phi = 0.f;
        {
            const float* vo = vown + vb*HHALF;
            #pragma unroll
            for (int kl = 0; kl < 16; kl++) {
                int kp = kl*4 + g;
                phi = fmaf(pwf[(own_base + kp)*PWSTR + hl], vo[kp], phi);
            }
            int buf = rc & 1;
            mbar_wait_cluster(mbar, rc & 1u); rc++;
            const float* vp = vpeer + buf*HHALF;
            #pragma unroll
            for (int kl = 0; kl < 16; kl++) {
                int kp = kl*4 + g;
                phi = fmaf(pwf[(peer_base + kp)*PWSTR + hl], vp[kp], phi);
            }
        }
        phi += __shfl_xor_sync(0xffffffffu, phi, 1);
        phi += __shfl_xor_sync(0xffffffffu, phi, 2);
        phi += pb;
        v += aa * __sinf(fmaf(om, (float)s, phi));

        // ---- self-attend: v += beta * (sigmoid(v) @ sa_W.T) ----
        float sg = fmaf(0.5f, tanhap(0.5f * v), 0.5f);
        if (g == 0) {
            sgown[hl] = sg;
            st_remote_f32(sgpeer_rm + ((sc & 1u)*HHALF + hl)*4u, sg);
            arrive_remote(mbar_rm);
        }
        sc++;
        __syncthreads();

        float acc = 0.f;
        #pragma unroll
        for (int kl = 0; kl < 16; kl++) {
            int kp = kl*4 + g;
            acc = fmaf(saf[(own_base + kp)*PWSTR + hl], sgown[kp], acc);
        }
        {
            int buf = rc & 1;
            mbar_wait_cluster(mbar, rc & 1u); rc++;
            const float* sp2 = sgpeer + buf*HHALF;
            #pragma unroll
            for (int kl = 0; kl < 16; kl++) {
                int kp = kl*4 + g;
                acc = fmaf(saf[(peer_base + kp)*PWSTR + hl], sp2[kp], acc);
            }
        }
        acc += __shfl_xor_sync(0xffffffffu, acc, 1);
        acc += __shfl_xor_sync(0xffffffffu, acc, 2);
        v = fmaf(bet, acc, v);

        vb ^= 1;
        if (g == 0) {
            out[(b*Ssz + s)*Hsz + habs] = v;
            vown[vb*HHALF + hl] = v;
            if (s + 1 < Ssz) {  // skip final unconsumed send (balances phases)
                st_remote_f32(vpeer_rm + ((sc & 1u)*HHALF + hl)*4u, v);
                arrive_remote(mbar_rm);
            }
        }
        sc++;
        __syncthreads();

        nb = nb_n; db = db_n;
    }

    if (write_hfinal && g == 0)
        out[Bsz*Ssz*Hsz + b*Hsz + habs] = v;

    asm volatile("barrier.cluster.arrive.aligned;" ::: "memory");
    asm volatile("barrier.cluster.wait.aligned;"   ::: "memory");
}

// ---------------- launch ----------------
extern "C" void kernel_launch(void* const* d_in, const int* in_sizes, int n_in,
                              void* d_out, int out_size)
{
    const float* x        = (const float*)d_in[0];
    const float* h0       = (const float*)d_in[1];
    const float* input_w  = (const float*)d_in[2];
    const float* input_b  = (const float*)d_in[3];
    const float* gleak    = (const float*)d_in[4];
    const float* vleak    = (const float*)d_in[5];
    const float* cm       = (const float*)d_in[6];
    const float* sigma    = (const float*)d_in[7];
    const float* mu       = (const float*)d_in[8];
    const float* w        = (const float*)d_in[9];
    const float* erev     = (const float*)d_in[10];
    const float* s_sigma  = (const float*)d_in[11];
    const float* s_mu     = (const float*)d_in[12];
    const float* s_w      = (const float*)d_in[13];
    const float* s_erev   = (const float*)d_in[14];
    const float* amplitude= (const float*)d_in[15];
    const float* omega    = (const float*)d_in[16];
    const float* phase_W  = (const float*)d_in[17];
    const float* phase_b  = (const float*)d_in[18];
    const float* alpha    = (const float*)d_in[19];
    const float* sa_W     = (const float*)d_in[20];
    const float* beta     = (const float*)d_in[21];
    float* out = (float*)d_out;

    const int smem_sens = 2*Isz*Hsz*4 + (128 + 512 + 512)*4;
    cudaFuncSetAttribute(sens_kernel, cudaFuncAttributeMaxDynamicSharedMemorySize, smem_sens);
    cudaFuncSetAttribute(seq_kernel,  cudaFuncAttributeMaxDynamicSharedMemorySize, SMEM_SEQ);

    prep_kernel<<<Hsz + Isz, Hsz>>>(sigma, mu, w, erev, s_sigma, s_mu, s_w, s_erev, input_w, input_b);
    prep2_kernel<<<1, Hsz>>>(gleak, vleak, cm, phase_W, sa_W);

    dim3 gb(Ssz, Bsz/16);
    sens_kernel<<<gb, 512, smem_sens>>>(x);

    int whf = (out_size >= Bsz*Ssz*Hsz + Bsz*Hsz) ? 1 : 0;
    seq_kernel<<<Bsz*2, SEQ_TPB, SMEM_SEQ>>>(h0, amplitude, omega, phase_b, alpha, beta, out, whf);
}

// round 4
// speedup vs baseline: 1.3883x; 1.3883x over previous
#include <cuda_runtime.h>
#include <cuda_bf16.h>
#include <cstdint>

#define Bsz 64
#define Ssz 256
#define Isz 128
#define Hsz 128
#define UNF 6

#define SEQ_TPB 512
#define HHALF 64
#define PWSTR 65    // floats per pwf/saf row

// ---------------- device scratch ----------------
__device__ float2 g_rab[Hsz*Hsz];       // (a,b): a=0.5*sigma, b=-0.5*sigma*mu, [src][dst]
__device__ float  g_rcs[Hsz*Hsz];       // 0.5*softplus(w)*erev, [src][dst]
__device__ float2 g_sab[Isz*Hsz];
__device__ float  g_scs[Isz*Hsz];
__device__ float  g_numconst[Hsz];
__device__ float  g_denconst[Hsz];
__device__ float  g_cmt[Hsz];
__device__ float  g_pwF[Hsz*Hsz];       // phase_W transposed [k][h]
__device__ float  g_saF[Hsz*Hsz];       // sa_W transposed [k][h]
__device__ float  g_numbase[Bsz*Ssz*Hsz];
__device__ float  g_denbase[Bsz*Ssz*Hsz];

// ---------------- helpers ----------------
__device__ __forceinline__ float sp(float x) { return log1pf(expf(x)); }
__device__ __forceinline__ float tanhap(float x) {
    float y; asm("tanh.approx.f32 %0, %1;" : "=f"(y) : "f"(x)); return y;
}
__device__ __forceinline__ float fabsb(float x) {
    return __int_as_float(__float_as_int(x) & 0x7fffffff);
}
__device__ __forceinline__ uint32_t smem_u32(const void* p) {
    uint32_t a; asm("{ .reg .u64 t; cvta.to.shared.u64 t, %1; cvt.u32.u64 %0, t; }" : "=r"(a) : "l"(p));
    return a;
}
__device__ __forceinline__ void mbar_init(uint32_t mbar, uint32_t cnt) {
    asm volatile("mbarrier.init.shared.b64 [%0], %1;" :: "r"(mbar), "r"(cnt) : "memory");
}
__device__ __forceinline__ void mbar_wait_cluster(uint32_t mbar, uint32_t par) {
    asm volatile(
        "{\n\t.reg .pred P;\n"
        "WL_%=:\n\t"
        "mbarrier.try_wait.parity.acquire.cluster.shared::cta.b64 P, [%0], %1, 0x989680;\n\t"
        "@!P bra WL_%=;\n\t}"
        :: "r"(mbar), "r"(par) : "memory");
}
__device__ __forceinline__ void st_remote_f32(uint32_t addr, float v) {
    asm volatile("st.shared::cluster.f32 [%0], %1;" :: "r"(addr), "f"(v) : "memory");
}
__device__ __forceinline__ void fence_arrive_remote(uint32_t mbar) {
    asm volatile("fence.acq_rel.cluster;" ::: "memory");
    asm volatile("mbarrier.arrive.release.cluster.shared::cluster.b64 _, [%0];" :: "r"(mbar) : "memory");
}

// ---------------- kernel A: per-edge param folding ----------------
__global__ void prep_kernel(const float* __restrict__ sigma, const float* __restrict__ mu,
                            const float* __restrict__ w,     const float* __restrict__ erev,
                            const float* __restrict__ s_sigma, const float* __restrict__ s_mu,
                            const float* __restrict__ s_w,   const float* __restrict__ s_erev,
                            const float* __restrict__ input_w, const float* __restrict__ input_b)
{
    int r = blockIdx.x, h = threadIdx.x;
    if (r < Hsz) {
        int idx = r*Hsz + h;
        float a = 0.5f * sigma[idx];
        g_rab[idx] = make_float2(a, -a * mu[idx]);
        g_rcs[idx] = 0.5f * sp(w[idx]) * erev[idx];
    } else {
        int i = r - Hsz;
        int idx = i*Hsz + h;
        float a = 0.5f * s_sigma[idx];
        g_sab[idx] = make_float2(a * input_w[i], a * (input_b[i] - s_mu[idx]));
        g_scs[idx] = 0.5f * sp(s_w[idx]) * s_erev[idx];
    }
}

// ---------------- kernel A2 ----------------
__global__ void prep2_kernel(const float* __restrict__ gleak, const float* __restrict__ vleak,
                             const float* __restrict__ cm,
                             const float* __restrict__ phase_W, const float* __restrict__ sa_W)
{
    int h = threadIdx.x;
    float nc = 0.f, dc = 0.f;
    for (int j = 0; j < Hsz; j++) { float cs = g_rcs[j*Hsz + h]; nc += cs; dc += fabsf(cs); }
    for (int i = 0; i < Isz; i++) { float cs = g_scs[i*Hsz + h]; nc += cs; dc += fabsf(cs); }
    float gl  = sp(gleak[h]);
    float cmt = sp(cm[h]) * (float)UNF;
    g_numconst[h] = gl * vleak[h] + nc;
    g_denconst[h] = cmt + gl + 1e-8f + dc;
    g_cmt[h] = cmt;
    for (int k = 0; k < Hsz; k++) {
        g_pwF[k*Hsz + h] = phase_W[h*Hsz + k];
        g_saF[k*Hsz + h] = sa_W[h*Hsz + k];
    }
}

// ---------------- kernel B: sensory pre-pass ----------------
__global__ __launch_bounds__(512, 1) void sens_kernel(const float* __restrict__ x)
{
    extern __shared__ float sm[];
    float2* sab = (float2*)sm;
    float*  xs  = sm + 2*Isz*Hsz;
    float*  pn  = xs + 128;
    float*  pd  = pn + 512;

    int tid = threadIdx.x;
    int h = tid & 127, g = tid >> 7;

    for (int r = tid; r < Isz*Hsz; r += 512) sab[r] = g_sab[r];

    float scs[32];
    #pragma unroll
    for (int il = 0; il < 32; il++) scs[il] = g_scs[(g*32 + il)*Hsz + h];

    float ncst = g_numconst[h], dcst = g_denconst[h];
    int s = blockIdx.x;

    for (int bb = 0; bb < 16; bb++) {
        int b = blockIdx.y * 16 + bb;
        __syncthreads();
        if (tid < Isz) xs[h] = x[(b*Ssz + s)*Isz + h];
        __syncthreads();
        float n = 0.f, d = 0.f;
        #pragma unroll
        for (int q = 0; q < 8; q++) {
            float4 x4 = *(const float4*)(xs + g*32 + 4*q);
            float xv[4] = {x4.x, x4.y, x4.z, x4.w};
            #pragma unroll
            for (int e = 0; e < 4; e++) {
                int il = 4*q + e;
                float2 p = sab[(g*32 + il)*Hsz + h];
                float t = tanhap(fmaf(p.x, xv[e], p.y));
                n = fmaf(scs[il], t, n);
                d = fmaf(fabsb(scs[il]), t, d);
            }
        }
        pn[g*Hsz + h] = n; pd[g*Hsz + h] = d;
        __syncthreads();
        if (g == 0) {
            float num = ncst + pn[h] + pn[Hsz + h] + pn[2*Hsz + h] + pn[3*Hsz + h];
            float den = dcst + pd[h] + pd[Hsz + h] + pd[2*Hsz + h] + pd[3*Hsz + h];
            int o = (b*Ssz + s)*Hsz + h;
            g_numbase[o] = num;
            g_denbase[o] = den;
        }
    }
}

// ---------------- smem byte offsets for seq kernel ----------------
#define OFF_PWF    0
#define OFF_SAF    33280                  // 128*65*4
#define OFF_VOWN   66560                  // + 128*65*4
#define OFF_VPEER  67072                  // + 2*64*4
#define OFF_SGOWN  67584                  // + 2*64*4
#define OFF_SGPEER 67840                  // + 64*4
#define OFF_MBAR   68352                  // + 2*64*4
#define SMEM_SEQ   68608

// ---------------- kernel C: sequential scan, 2-CTA cluster, 512 thr ----------------
__global__ __launch_bounds__(SEQ_TPB, 1) __cluster_dims__(2, 1, 1)
void seq_kernel(const float* __restrict__ h0, const float* __restrict__ amplitude,
                const float* __restrict__ omega, const float* __restrict__ phase_b,
                const float* __restrict__ alpha_p, const float* __restrict__ beta_p,
                float* __restrict__ out, int write_hfinal)
{
    extern __shared__ char smc[];
    float* pwf    = (float*)(smc + OFF_PWF);      // [128][PWSTR]
    float* saf    = (float*)(smc + OFF_SAF);      // [128][PWSTR]
    float* vown   = (float*)(smc + OFF_VOWN);     // [2][64]
    float* vpeer  = (float*)(smc + OFF_VPEER);    // [2][64]
    float* sgown  = (float*)(smc + OFF_SGOWN);    // [64]
    float* sgpeer = (float*)(smc + OFF_SGPEER);   // [2][64]

    uint32_t sbase = smem_u32(smc);
    uint32_t mbar  = sbase + OFF_MBAR;

    uint32_t rank; asm("mov.u32 %0, %%cluster_ctarank;" : "=r"(rank));
    uint32_t peerR = rank ^ 1u;
    int b = blockIdx.x >> 1;
    int own_base  = (int)rank * HHALF;
    int peer_base = (int)peerR * HHALF;

    int tid  = threadIdx.x;
    int lane = tid & 31;
    int warp = tid >> 5;
    int g    = lane & 7;                      // src subgroup 0..7
    int hl   = (warp << 2) | (lane >> 3);     // 0..63 local dst
    int habs = own_base + hl;

    // smem preload: epilogue weights (own dst columns)
    for (int idx = tid; idx < Hsz*HHALF; idx += SEQ_TPB) {
        int k = idx >> 6, c = idx & 63;
        pwf[k*PWSTR + c] = g_pwF[k*Hsz + own_base + c];
        saf[k*PWSTR + c] = g_saF[k*Hsz + own_base + c];
    }

    // per-thread edge params in registers: srcs j = base + jl*8 + g
    float ao[8], bo[8], cso[8], ap[8], bp[8], csp[8];
    #pragma unroll
    for (int jl = 0; jl < 8; jl++) {
        int jo = own_base  + jl*8 + g;
        int jp = peer_base + jl*8 + g;
        float2 r0 = g_rab[jo*Hsz + habs];
        float2 r1 = g_rab[jp*Hsz + habs];
        ao[jl] = r0.x; bo[jl] = r0.y; cso[jl] = g_rcs[jo*Hsz + habs];
        ap[jl] = r1.x; bp[jl] = r1.y; csp[jl] = g_rcs[jp*Hsz + habs];
    }
    float cmt = g_cmt[habs];
    float aa  = alpha_p[0] * amplitude[habs];
    float om  = omega[habs];
    float pb  = phase_b[habs];
    float bet = beta_p[0];

    if (tid == 0) mbar_init(mbar, 1);
    __syncthreads();
    asm volatile("barrier.cluster.arrive.aligned;" ::: "memory");
    asm volatile("barrier.cluster.wait.aligned;"   ::: "memory");

    uint32_t vpeer_rm, sgpeer_rm, mbar_rm;
    asm("mapa.shared::cluster.u32 %0, %1, %2;" : "=r"(vpeer_rm)  : "r"(sbase + OFF_VPEER),  "r"(peerR));
    asm("mapa.shared::cluster.u32 %0, %1, %2;" : "=r"(sgpeer_rm) : "r"(sbase + OFF_SGPEER), "r"(peerR));
    asm("mapa.shared::cluster.u32 %0, %1, %2;" : "=r"(mbar_rm)   : "r"(sbase + OFF_MBAR),   "r"(peerR));

    float v = h0[b*Hsz + habs];
    int vb = 0;
    uint32_t sc = 0, rc = 0;

    // init exchange: publish h0 own half (send #0)
    if (g == 0) {
        vown[vb*HHALF + hl] = v;
        st_remote_f32(vpeer_rm + ((sc & 1u)*HHALF + hl)*4u, v);
    }
    __syncthreads();
    if (tid == 0) fence_arrive_remote(mbar_rm);
    sc++;

    float nb = g_numbase[(b*Ssz)*Hsz + habs];
    float db = g_denbase[(b*Ssz)*Hsz + habs];

    for (int s = 0; s < Ssz; s++) {
        float nb_n = 0.f, db_n = 0.f;
        if (s + 1 < Ssz) {
            nb_n = g_numbase[(b*Ssz + s + 1)*Hsz + habs];
            db_n = g_denbase[(b*Ssz + s + 1)*Hsz + habs];
        }

        #pragma unroll 1
        for (int u = 0; u < UNF; u++) {
            float n = 0.f, d = 0.f;
            // own-half srcs (local) — overlaps peer's in-flight exchange
            const float* vo = vown + vb*HHALF;
            #pragma unroll
            for (int jl = 0; jl < 8; jl++) {
                float vv = vo[jl*8 + g];
                float t = tanhap(fmaf(ao[jl], vv, bo[jl]));
                n = fmaf(cso[jl], t, n);
                d = fmaf(fabsb(cso[jl]), t, d);
            }
            // receive peer half
            int buf = rc & 1;
            mbar_wait_cluster(mbar, rc & 1u); rc++;
            const float* vp = vpeer + buf*HHALF;
            #pragma unroll
            for (int jl = 0; jl < 8; jl++) {
                float vv = vp[jl*8 + g];
                float t = tanhap(fmaf(ap[jl], vv, bp[jl]));
                n = fmaf(csp[jl], t, n);
                d = fmaf(fabsb(csp[jl]), t, d);
            }
            n += __shfl_xor_sync(0xffffffffu, n, 1);
            n += __shfl_xor_sync(0xffffffffu, n, 2);
            n += __shfl_xor_sync(0xffffffffu, n, 4);
            d += __shfl_xor_sync(0xffffffffu, d, 1);
            d += __shfl_xor_sync(0xffffffffu, d, 2);
            d += __shfl_xor_sync(0xffffffffu, d, 4);
            v = __fdividef(fmaf(cmt, v, nb + n), db + d);
            vb ^= 1;
            if (g == 0) {
                vown[vb*HHALF + hl] = v;
                st_remote_f32(vpeer_rm + ((sc & 1u)*HHALF + hl)*4u, v);
            }
            __syncthreads();
            if (tid == 0) fence_arrive_remote(mbar_rm);
            sc++;
        }

        // ---- pulse: phi = v @ phase_W.T + phase_b ----
        float phi = 0.f;
        {
            const float* vo = vown + vb*HHALF;
            #pragma unroll
            for (int kl = 0; kl < 8; kl++) {
                int kp = kl*8 + g;
                phi = fmaf(pwf[(own_base + kp)*PWSTR + hl], vo[kp], phi);
            }
            int buf = rc & 1;
            mbar_wait_cluster(mbar, rc & 1u); rc++;
            const float* vp = vpeer + buf*HHALF;
            #pragma unroll
            for (int kl = 0; kl < 8; kl++) {
                int kp = kl*8 + g;
                phi = fmaf(pwf[(peer_base + kp)*PWSTR + hl], vp[kp], phi);
            }
        }
        phi += __shfl_xor_sync(0xffffffffu, phi, 1);
        phi += __shfl_xor_sync(0xffffffffu, phi, 2);
        phi += __shfl_xor_sync(0xffffffffu, phi, 4);
        phi += pb;
        v += aa * __sinf(fmaf(om, (float)s, phi));

        // ---- self-attend exchange ----
        float sg = fmaf(0.5f, tanhap(0.5f * v), 0.5f);
        if (g == 0) {
            sgown[hl] = sg;
            st_remote_f32(sgpeer_rm + ((sc & 1u)*HHALF + hl)*4u, sg);
        }
        __syncthreads();
        if (tid == 0) fence_arrive_remote(mbar_rm);
        sc++;

        float acc = 0.f;
        #pragma unroll
        for (int kl = 0; kl < 8; kl++) {
            int kp = kl*8 + g;
            acc = fmaf(saf[(own_base + kp)*PWSTR + hl], sgown[kp], acc);
        }
        {
            int buf = rc & 1;
            mbar_wait_cluster(mbar, rc & 1u); rc++;
            const float* sp2 = sgpeer + buf*HHALF;
            #pragma unroll
            for (int kl = 0; kl < 8; kl++) {
                int kp = kl*8 + g;
                acc = fmaf(saf[(peer_base + kp)*PWSTR + hl], sp2[kp], acc);
            }
        }
        acc += __shfl_xor_sync(0xffffffffu, acc, 1);
        acc += __shfl_xor_sync(0xffffffffu, acc, 2);
        acc += __shfl_xor_sync(0xffffffffu, acc, 4);
        v = fmaf(bet, acc, v);

        vb ^= 1;
        bool last = (s + 1 == Ssz);
        if (g == 0) {
            out[(b*Ssz + s)*Hsz + habs] = v;
            vown[vb*HHALF + hl] = v;
            if (!last)
                st_remote_f32(vpeer_rm + ((sc & 1u)*HHALF + hl)*4u, v);
        }
        __syncthreads();
        if (tid == 0 && !last) fence_arrive_remote(mbar_rm);
        sc++;

        nb = nb_n; db = db_n;
    }

    if (write_hfinal && g == 0)
        out[Bsz*Ssz*Hsz + b*Hsz + habs] = v;

    asm volatile("barrier.cluster.arrive.aligned;" ::: "memory");
    asm volatile("barrier.cluster.wait.aligned;"   ::: "memory");
}

// ---------------- launch ----------------
extern "C" void kernel_launch(void* const* d_in, const int* in_sizes, int n_in,
                              void* d_out, int out_size)
{
    const float* x        = (const float*)d_in[0];
    const float* h0       = (const float*)d_in[1];
    const float* input_w  = (const float*)d_in[2];
    const float* input_b  = (const float*)d_in[3];
    const float* gleak    = (const float*)d_in[4];
    const float* vleak    = (const float*)d_in[5];
    const float* cm       = (const float*)d_in[6];
    const float* sigma    = (const float*)d_in[7];
    const float* mu       = (const float*)d_in[8];
    const float* w        = (const float*)d_in[9];
    const float* erev     = (const float*)d_in[10];
    const float* s_sigma  = (const float*)d_in[11];
    const float* s_mu     = (const float*)d_in[12];
    const float* s_w      = (const float*)d_in[13];
    const float* s_erev   = (const float*)d_in[14];
    const float* amplitude= (const float*)d_in[15];
    const float* omega    = (const float*)d_in[16];
    const float* phase_W  = (const float*)d_in[17];
    const float* phase_b  = (const float*)d_in[18];
    const float* alpha    = (const float*)d_in[19];
    const float* sa_W     = (const float*)d_in[20];
    const float* beta     = (const float*)d_in[21];
    float* out = (float*)d_out;

    const int smem_sens = 2*Isz*Hsz*4 + (128 + 512 + 512)*4;
    cudaFuncSetAttribute(sens_kernel, cudaFuncAttributeMaxDynamicSharedMemorySize, smem_sens);
    cudaFuncSetAttribute(seq_kernel,  cudaFuncAttributeMaxDynamicSharedMemorySize, SMEM_SEQ);

    prep_kernel<<<Hsz + Isz, Hsz>>>(sigma, mu, w, erev, s_sigma, s_mu, s_w, s_erev, input_w, input_b);
    prep2_kernel<<<1, Hsz>>>(gleak, vleak, cm, phase_W, sa_W);

    dim3 gb(Ssz, Bsz/16);
    sens_kernel<<<gb, 512, smem_sens>>>(x);

    int whf = (out_size >= Bsz*Ssz*Hsz + Bsz*Hsz) ? 1 : 0;
    seq_kernel<<<Bsz*2, SEQ_TPB, SMEM_SEQ>>>(h0, amplitude, omega, phase_b, alpha, beta, out, whf);
}

// round 5
// speedup vs baseline: 1.5192x; 1.0943x over previous
#include <cuda_runtime.h>
#include <cuda_bf16.h>
#include <cstdint>

#define Bsz 64
#define Ssz 256
#define Isz 128
#define Hsz 128
#define UNF 6

#define SEQ_TPB 512
#define HHALF 64
#define PWSTR 65    // floats per pwf/saf row

// ---------------- device scratch ----------------
__device__ float2 g_rab[Hsz*Hsz];       // (a,b): a=0.5*sigma, b=-0.5*sigma*mu, [src][dst]
__device__ float  g_rcs[Hsz*Hsz];       // 0.5*softplus(w)*erev, [src][dst]
__device__ float2 g_sab[Isz*Hsz];
__device__ float  g_scs[Isz*Hsz];
__device__ float  g_numconst[Hsz];
__device__ float  g_denconst[Hsz];
__device__ float  g_cmt[Hsz];
__device__ float  g_pwF[Hsz*Hsz];       // phase_W transposed [k][h]
__device__ float  g_saF[Hsz*Hsz];       // sa_W transposed [k][h]
__device__ float  g_numbase[Bsz*Ssz*Hsz];
__device__ float  g_denbase[Bsz*Ssz*Hsz];

// ---------------- helpers ----------------
__device__ __forceinline__ float sp(float x) { return log1pf(expf(x)); }
__device__ __forceinline__ float tanhap(float x) {
    float y; asm("tanh.approx.f32 %0, %1;" : "=f"(y) : "f"(x)); return y;
}
__device__ __forceinline__ float fabsb(float x) {
    return __int_as_float(__float_as_int(x) & 0x7fffffff);
}
__device__ __forceinline__ uint32_t smem_u32(const void* p) {
    uint32_t a; asm("{ .reg .u64 t; cvta.to.shared.u64 t, %1; cvt.u32.u64 %0, t; }" : "=r"(a) : "l"(p));
    return a;
}
__device__ __forceinline__ void mbar_init(uint32_t mbar, uint32_t cnt) {
    asm volatile("mbarrier.init.shared.b64 [%0], %1;" :: "r"(mbar), "r"(cnt) : "memory");
}
__device__ __forceinline__ void mbar_wait_cluster(uint32_t mbar, uint32_t par) {
    asm volatile(
        "{\n\t.reg .pred P;\n"
        "WL_%=:\n\t"
        "mbarrier.try_wait.parity.acquire.cluster.shared::cta.b64 P, [%0], %1, 0x989680;\n\t"
        "@!P bra WL_%=;\n\t}"
        :: "r"(mbar), "r"(par) : "memory");
}
// writer-thread pattern: remote store, then SAME thread's release-arrive
// (orders its own prior st.shared::cluster; NO fence -> NO CCTL.IVALL L1 flush)
__device__ __forceinline__ void st_remote_f32(uint32_t addr, float v) {
    asm volatile("st.shared::cluster.f32 [%0], %1;" :: "r"(addr), "f"(v) : "memory");
}
__device__ __forceinline__ void arrive_remote(uint32_t mbar) {
    asm volatile("mbarrier.arrive.release.cluster.shared::cluster.b64 _, [%0];" :: "r"(mbar) : "memory");
}

// ---------------- kernel A: per-edge param folding ----------------
__global__ void prep_kernel(const float* __restrict__ sigma, const float* __restrict__ mu,
                            const float* __restrict__ w,     const float* __restrict__ erev,
                            const float* __restrict__ s_sigma, const float* __restrict__ s_mu,
                            const float* __restrict__ s_w,   const float* __restrict__ s_erev,
                            const float* __restrict__ input_w, const float* __restrict__ input_b)
{
    int r = blockIdx.x, h = threadIdx.x;
    if (r < Hsz) {
        int idx = r*Hsz + h;
        float a = 0.5f * sigma[idx];
        g_rab[idx] = make_float2(a, -a * mu[idx]);
        g_rcs[idx] = 0.5f * sp(w[idx]) * erev[idx];
    } else {
        int i = r - Hsz;
        int idx = i*Hsz + h;
        float a = 0.5f * s_sigma[idx];
        g_sab[idx] = make_float2(a * input_w[i], a * (input_b[i] - s_mu[idx]));
        g_scs[idx] = 0.5f * sp(s_w[idx]) * s_erev[idx];
    }
}

// ---------------- kernel A2 ----------------
__global__ void prep2_kernel(const float* __restrict__ gleak, const float* __restrict__ vleak,
                             const float* __restrict__ cm,
                             const float* __restrict__ phase_W, const float* __restrict__ sa_W)
{
    int h = threadIdx.x;
    float nc = 0.f, dc = 0.f;
    for (int j = 0; j < Hsz; j++) { float cs = g_rcs[j*Hsz + h]; nc += cs; dc += fabsf(cs); }
    for (int i = 0; i < Isz; i++) { float cs = g_scs[i*Hsz + h]; nc += cs; dc += fabsf(cs); }
    float gl  = sp(gleak[h]);
    float cmt = sp(cm[h]) * (float)UNF;
    g_numconst[h] = gl * vleak[h] + nc;
    g_denconst[h] = cmt + gl + 1e-8f + dc;
    g_cmt[h] = cmt;
    for (int k = 0; k < Hsz; k++) {
        g_pwF[k*Hsz + h] = phase_W[h*Hsz + k];
        g_saF[k*Hsz + h] = sa_W[h*Hsz + k];
    }
}

// ---------------- kernel B: sensory pre-pass ----------------
__global__ __launch_bounds__(512, 1) void sens_kernel(const float* __restrict__ x)
{
    extern __shared__ float sm[];
    float2* sab = (float2*)sm;
    float*  xs  = sm + 2*Isz*Hsz;
    float*  pn  = xs + 128;
    float*  pd  = pn + 512;

    int tid = threadIdx.x;
    int h = tid & 127, g = tid >> 7;

    for (int r = tid; r < Isz*Hsz; r += 512) sab[r] = g_sab[r];

    float scs[32];
    #pragma unroll
    for (int il = 0; il < 32; il++) scs[il] = g_scs[(g*32 + il)*Hsz + h];

    float ncst = g_numconst[h], dcst = g_denconst[h];
    int s = blockIdx.x;

    for (int bb = 0; bb < 16; bb++) {
        int b = blockIdx.y * 16 + bb;
        __syncthreads();
        if (tid < Isz) xs[h] = x[(b*Ssz + s)*Isz + h];
        __syncthreads();
        float n = 0.f, d = 0.f;
        #pragma unroll
        for (int q = 0; q < 8; q++) {
            float4 x4 = *(const float4*)(xs + g*32 + 4*q);
            float xv[4] = {x4.x, x4.y, x4.z, x4.w};
            #pragma unroll
            for (int e = 0; e < 4; e++) {
                int il = 4*q + e;
                float2 p = sab[(g*32 + il)*Hsz + h];
                float t = tanhap(fmaf(p.x, xv[e], p.y));
                n = fmaf(scs[il], t, n);
                d = fmaf(fabsb(scs[il]), t, d);
            }
        }
        pn[g*Hsz + h] = n; pd[g*Hsz + h] = d;
        __syncthreads();
        if (g == 0) {
            float num = ncst + pn[h] + pn[Hsz + h] + pn[2*Hsz + h] + pn[3*Hsz + h];
            float den = dcst + pd[h] + pd[Hsz + h] + pd[2*Hsz + h] + pd[3*Hsz + h];
            int o = (b*Ssz + s)*Hsz + h;
            g_numbase[o] = num;
            g_denbase[o] = den;
        }
    }
}

// ---------------- smem byte offsets for seq kernel ----------------
#define OFF_PWF    0
#define OFF_SAF    33280                  // 128*65*4
#define OFF_VOWN   66560                  // + 128*65*4
#define OFF_VPEER  67072                  // + 2*64*4
#define OFF_SGOWN  67584                  // + 2*64*4
#define OFF_SGPEER 67840                  // + 64*4
#define OFF_MBAR   68352                  // + 2*64*4
#define SMEM_SEQ   68608

// ---------------- kernel C: sequential scan, 2-CTA cluster, fence-free exchange ----------------
__global__ __launch_bounds__(SEQ_TPB, 1) __cluster_dims__(2, 1, 1)
void seq_kernel(const float* __restrict__ h0, const float* __restrict__ amplitude,
                const float* __restrict__ omega, const float* __restrict__ phase_b,
                const float* __restrict__ alpha_p, const float* __restrict__ beta_p,
                float* __restrict__ out, int write_hfinal)
{
    extern __shared__ char smc[];
    float* pwf    = (float*)(smc + OFF_PWF);      // [128][PWSTR]
    float* saf    = (float*)(smc + OFF_SAF);      // [128][PWSTR]
    float* vown   = (float*)(smc + OFF_VOWN);     // [2][64]
    float* vpeer  = (float*)(smc + OFF_VPEER);    // [2][64]
    float* sgown  = (float*)(smc + OFF_SGOWN);    // [64]
    float* sgpeer = (float*)(smc + OFF_SGPEER);   // [2][64]

    uint32_t sbase = smem_u32(smc);
    uint32_t mbar  = sbase + OFF_MBAR;

    uint32_t rank; asm("mov.u32 %0, %%cluster_ctarank;" : "=r"(rank));
    uint32_t peerR = rank ^ 1u;
    int b = blockIdx.x >> 1;
    int own_base  = (int)rank * HHALF;
    int peer_base = (int)peerR * HHALF;

    int tid  = threadIdx.x;
    int lane = tid & 31;
    int warp = tid >> 5;
    int g    = lane & 7;                      // src subgroup 0..7
    int hl   = (warp << 2) | (lane >> 3);     // 0..63 local dst
    int habs = own_base + hl;

    // smem preload: epilogue weights (own dst columns)
    for (int idx = tid; idx < Hsz*HHALF; idx += SEQ_TPB) {
        int k = idx >> 6, c = idx & 63;
        pwf[k*PWSTR + c] = g_pwF[k*Hsz + own_base + c];
        saf[k*PWSTR + c] = g_saF[k*Hsz + own_base + c];
    }

    // per-thread edge params in registers: srcs j = base + jl*8 + g
    float ao[8], bo[8], cso[8], ap[8], bp[8], csp[8];
    #pragma unroll
    for (int jl = 0; jl < 8; jl++) {
        int jo = own_base  + jl*8 + g;
        int jp = peer_base + jl*8 + g;
        float2 r0 = g_rab[jo*Hsz + habs];
        float2 r1 = g_rab[jp*Hsz + habs];
        ao[jl] = r0.x; bo[jl] = r0.y; cso[jl] = g_rcs[jo*Hsz + habs];
        ap[jl] = r1.x; bp[jl] = r1.y; csp[jl] = g_rcs[jp*Hsz + habs];
    }
    float cmt = g_cmt[habs];
    float aa  = alpha_p[0] * amplitude[habs];
    float om  = omega[habs];
    float pb  = phase_b[habs];
    float bet = beta_p[0];

    if (tid == 0) mbar_init(mbar, 64);        // 64 writer arrives per phase
    __syncthreads();
    asm volatile("barrier.cluster.arrive.aligned;" ::: "memory");
    asm volatile("barrier.cluster.wait.aligned;"   ::: "memory");

    uint32_t vpeer_rm, sgpeer_rm, mbar_rm;
    asm("mapa.shared::cluster.u32 %0, %1, %2;" : "=r"(vpeer_rm)  : "r"(sbase + OFF_VPEER),  "r"(peerR));
    asm("mapa.shared::cluster.u32 %0, %1, %2;" : "=r"(sgpeer_rm) : "r"(sbase + OFF_SGPEER), "r"(peerR));
    asm("mapa.shared::cluster.u32 %0, %1, %2;" : "=r"(mbar_rm)   : "r"(sbase + OFF_MBAR),   "r"(peerR));

    float v = h0[b*Hsz + habs];
    int vb = 0;
    uint32_t sc = 0, rc = 0;

    // init exchange: publish h0 own half (send #0): per-writer store + release-arrive
    if (g == 0) {
        vown[vb*HHALF + hl] = v;
        st_remote_f32(vpeer_rm + ((sc & 1u)*HHALF + hl)*4u, v);
        arrive_remote(mbar_rm);
    }
    sc++;
    __syncthreads();

    float nb = g_numbase[(b*Ssz)*Hsz + habs];
    float db = g_denbase[(b*Ssz)*Hsz + habs];

    for (int s = 0; s < Ssz; s++) {
        float nb_n = 0.f, db_n = 0.f;
        if (s + 1 < Ssz) {
            nb_n = g_numbase[(b*Ssz + s + 1)*Hsz + habs];
            db_n = g_denbase[(b*Ssz + s + 1)*Hsz + habs];
        }

        #pragma unroll 1
        for (int u = 0; u < UNF; u++) {
            float n = 0.f, d = 0.f;
            // own-half srcs (local) — overlaps peer's in-flight exchange
            const float* vo = vown + vb*HHALF;
            #pragma unroll
            for (int jl = 0; jl < 8; jl++) {
                float vv = vo[jl*8 + g];
                float t = tanhap(fmaf(ao[jl], vv, bo[jl]));
                n = fmaf(cso[jl], t, n);
                d = fmaf(fabsb(cso[jl]), t, d);
            }
            // receive peer half
            int buf = rc & 1;
            mbar_wait_cluster(mbar, rc & 1u); rc++;
            const float* vp = vpeer + buf*HHALF;
            #pragma unroll
            for (int jl = 0; jl < 8; jl++) {
                float vv = vp[jl*8 + g];
                float t = tanhap(fmaf(ap[jl], vv, bp[jl]));
                n = fmaf(csp[jl], t, n);
                d = fmaf(fabsb(csp[jl]), t, d);
            }
            n += __shfl_xor_sync(0xffffffffu, n, 1);
            n += __shfl_xor_sync(0xffffffffu, n, 2);
            n += __shfl_xor_sync(0xffffffffu, n, 4);
            d += __shfl_xor_sync(0xffffffffu, d, 1);
            d += __shfl_xor_sync(0xffffffffu, d, 2);
            d += __shfl_xor_sync(0xffffffffu, d, 4);
            v = __fdividef(fmaf(cmt, v, nb + n), db + d);
            vb ^= 1;
            if (g == 0) {
                vown[vb*HHALF + hl] = v;
                st_remote_f32(vpeer_rm + ((sc & 1u)*HHALF + hl)*4u, v);
                arrive_remote(mbar_rm);
            }
            sc++;
            __syncthreads();
        }

        // ---- pulse: phi = v @ phase_W.T + phase_b ----
        float phi = 0.f;
        {
            const float* vo = vown + vb*HHALF;
            #pragma unroll
            for (int kl = 0; kl < 8; kl++) {
                int kp = kl*8 + g;
                phi = fmaf(pwf[(own_base + kp)*PWSTR + hl], vo[kp], phi);
            }
            int buf = rc & 1;
            mbar_wait_cluster(mbar, rc & 1u); rc++;
            const float* vp = vpeer + buf*HHALF;
            #pragma unroll
            for (int kl = 0; kl < 8; kl++) {
                int kp = kl*8 + g;
                phi = fmaf(pwf[(peer_base + kp)*PWSTR + hl], vp[kp], phi);
            }
        }
        phi += __shfl_xor_sync(0xffffffffu, phi, 1);
        phi += __shfl_xor_sync(0xffffffffu, phi, 2);
        phi += __shfl_xor_sync(0xffffffffu, phi, 4);
        phi += pb;
        v += aa * __sinf(fmaf(om, (float)s, phi));

        // ---- self-attend exchange ----
        float sg = fmaf(0.5f, tanhap(0.5f * v), 0.5f);
        if (g == 0) {
            sgown[hl] = sg;
            st_remote_f32(sgpeer_rm + ((sc & 1u)*HHALF + hl)*4u, sg);
            arrive_remote(mbar_rm);
        }
        sc++;
        __syncthreads();

        float acc = 0.f;
        #pragma unroll
        for (int kl = 0; kl < 8; kl++) {
            int kp = kl*8 + g;
            acc = fmaf(saf[(own_base + kp)*PWSTR + hl], sgown[kp], acc);
        }
        {
            int buf = rc & 1;
            mbar_wait_cluster(mbar, rc & 1u); rc++;
            const float* sp2 = sgpeer + buf*HHALF;
            #pragma unroll
            for (int kl = 0; kl < 8; kl++) {
                int kp = kl*8 + g;
                acc = fmaf(saf[(peer_base + kp)*PWSTR + hl], sp2[kp], acc);
            }
        }
        acc += __shfl_xor_sync(0xffffffffu, acc, 1);
        acc += __shfl_xor_sync(0xffffffffu, acc, 2);
        acc += __shfl_xor_sync(0xffffffffu, acc, 4);
        v = fmaf(bet, acc, v);

        vb ^= 1;
        bool last = (s + 1 == Ssz);
        if (g == 0) {
            out[(b*Ssz + s)*Hsz + habs] = v;
            vown[vb*HHALF + hl] = v;
            if (!last) {
                st_remote_f32(vpeer_rm + ((sc & 1u)*HHALF + hl)*4u, v);
                arrive_remote(mbar_rm);
            }
        }
        sc++;
        __syncthreads();

        nb = nb_n; db = db_n;
    }

    if (write_hfinal && g == 0)
        out[Bsz*Ssz*Hsz + b*Hsz + habs] = v;

    asm volatile("barrier.cluster.arrive.aligned;" ::: "memory");
    asm volatile("barrier.cluster.wait.aligned;"   ::: "memory");
}

// ---------------- launch ----------------
extern "C" void kernel_launch(void* const* d_in, const int* in_sizes, int n_in,
                              void* d_out, int out_size)
{
    const float* x        = (const float*)d_in[0];
    const float* h0       = (const float*)d_in[1];
    const float* input_w  = (const float*)d_in[2];
    const float* input_b  = (const float*)d_in[3];
    const float* gleak    = (const float*)d_in[4];
    const float* vleak    = (const float*)d_in[5];
    const float* cm       = (const float*)d_in[6];
    const float* sigma    = (const float*)d_in[7];
    const float* mu       = (const float*)d_in[8];
    const float* w        = (const float*)d_in[9];
    const float* erev     = (const float*)d_in[10];
    const float* s_sigma  = (const float*)d_in[11];
    const float* s_mu     = (const float*)d_in[12];
    const float* s_w      = (const float*)d_in[13];
    const float* s_erev   = (const float*)d_in[14];
    const float* amplitude= (const float*)d_in[15];
    const float* omega    = (const float*)d_in[16];
    const float* phase_W  = (const float*)d_in[17];
    const float* phase_b  = (const float*)d_in[18];
    const float* alpha    = (const float*)d_in[19];
    const float* sa_W     = (const float*)d_in[20];
    const float* beta     = (const float*)d_in[21];
    float* out = (float*)d_out;

    const int smem_sens = 2*Isz*Hsz*4 + (128 + 512 + 512)*4;
    cudaFuncSetAttribute(sens_kernel, cudaFuncAttributeMaxDynamicSharedMemorySize, smem_sens);
    cudaFuncSetAttribute(seq_kernel,  cudaFuncAttributeMaxDynamicSharedMemorySize, SMEM_SEQ);

    prep_kernel<<<Hsz + Isz, Hsz>>>(sigma, mu, w, erev, s_sigma, s_mu, s_w, s_erev, input_w, input_b);
    prep2_kernel<<<1, Hsz>>>(gleak, vleak, cm, phase_W, sa_W);

    dim3 gb(Ssz, Bsz/16);
    sens_kernel<<<gb, 512, smem_sens>>>(x);

    int whf = (out_size >= Bsz*Ssz*Hsz + Bsz*Hsz) ? 1 : 0;
    seq_kernel<<<Bsz*2, SEQ_TPB, SMEM_SEQ>>>(h0, amplitude, omega, phase_b, alpha, beta, out, whf);
}

// round 6
// speedup vs baseline: 2.3081x; 1.5193x over previous
#include <cuda_runtime.h>
#include <cuda_bf16.h>
#include <cstdint>

#define Bsz 64
#define Ssz 256
#define Isz 128
#define Hsz 128
#define UNF 6

#define SEQ_TPB 512
#define HHALF 64

// ---------------- device scratch ----------------
__device__ float2 g_rab[Hsz*Hsz];       // (a,b): a=0.5*sigma, b=-0.5*sigma*mu, [src][dst]
__device__ float  g_rcs[Hsz*Hsz];       // 0.5*softplus(w)*erev, [src][dst]
__device__ float2 g_sab[Isz*Hsz];
__device__ float  g_scs[Isz*Hsz];
__device__ float  g_numconst[Hsz];
__device__ float  g_denconst[Hsz];
__device__ float  g_cmt[Hsz];
__device__ float  g_pwF[Hsz*Hsz];       // phase_W transposed [k][h]
__device__ float  g_saF[Hsz*Hsz];       // sa_W transposed [k][h]
__device__ float  g_numbase[Bsz*Ssz*Hsz];
__device__ float  g_denbase[Bsz*Ssz*Hsz];

// ---------------- helpers ----------------
__device__ __forceinline__ float sp(float x) { return log1pf(expf(x)); }
__device__ __forceinline__ float tanhap(float x) {
    float y; asm("tanh.approx.f32 %0, %1;" : "=f"(y) : "f"(x)); return y;
}
__device__ __forceinline__ float fabsb(float x) {
    return __int_as_float(__float_as_int(x) & 0x7fffffff);
}
__device__ __forceinline__ uint32_t smem_u32(const void* p) {
    uint32_t a; asm("{ .reg .u64 t; cvta.to.shared.u64 t, %1; cvt.u32.u64 %0, t; }" : "=r"(a) : "l"(p));
    return a;
}
__device__ __forceinline__ void mbar_init(uint32_t mbar, uint32_t cnt) {
    asm volatile("mbarrier.init.shared.b64 [%0], %1;" :: "r"(mbar), "r"(cnt) : "memory");
}
__device__ __forceinline__ void mbar_expect_tx(uint32_t mbar, uint32_t bytes) {
    asm volatile("mbarrier.arrive.expect_tx.shared.b64 _, [%0], %1;" :: "r"(mbar), "r"(bytes) : "memory");
}
__device__ __forceinline__ void mbar_wait_cluster(uint32_t mbar, uint32_t par) {
    asm volatile(
        "{\n\t.reg .pred P;\n"
        "WL_%=:\n\t"
        "mbarrier.try_wait.parity.acquire.cluster.shared::cta.b64 P, [%0], %1, 0x989680;\n\t"
        "@!P bra WL_%=;\n\t}"
        :: "r"(mbar), "r"(par) : "memory");
}
// one-shot 256B push of our v-half into the peer's buffer; HW complete_tx on peer mbar
__device__ __forceinline__ void bulk_to_peer(uint32_t dst_cluster, uint32_t src_cta,
                                             uint32_t bytes, uint32_t mbar_cluster) {
    asm volatile("fence.proxy.async.shared::cta;" ::: "memory");
    asm volatile("cp.async.bulk.shared::cluster.shared::cta.mbarrier::complete_tx::bytes "
                 "[%0], [%1], %2, [%3];"
                 :: "r"(dst_cluster), "r"(src_cta), "r"(bytes), "r"(mbar_cluster) : "memory");
}

// ---------------- kernel A: per-edge param folding ----------------
__global__ void prep_kernel(const float* __restrict__ sigma, const float* __restrict__ mu,
                            const float* __restrict__ w,     const float* __restrict__ erev,
                            const float* __restrict__ s_sigma, const float* __restrict__ s_mu,
                            const float* __restrict__ s_w,   const float* __restrict__ s_erev,
                            const float* __restrict__ input_w, const float* __restrict__ input_b)
{
    int r = blockIdx.x, h = threadIdx.x;
    if (r < Hsz) {
        int idx = r*Hsz + h;
        float a = 0.5f * sigma[idx];
        g_rab[idx] = make_float2(a, -a * mu[idx]);
        g_rcs[idx] = 0.5f * sp(w[idx]) * erev[idx];
    } else {
        int i = r - Hsz;
        int idx = i*Hsz + h;
        float a = 0.5f * s_sigma[idx];
        g_sab[idx] = make_float2(a * input_w[i], a * (input_b[i] - s_mu[idx]));
        g_scs[idx] = 0.5f * sp(s_w[idx]) * s_erev[idx];
    }
}

// ---------------- kernel A2 ----------------
__global__ void prep2_kernel(const float* __restrict__ gleak, const float* __restrict__ vleak,
                             const float* __restrict__ cm,
                             const float* __restrict__ phase_W, const float* __restrict__ sa_W)
{
    int h = threadIdx.x;
    float nc = 0.f, dc = 0.f;
    for (int j = 0; j < Hsz; j++) { float cs = g_rcs[j*Hsz + h]; nc += cs; dc += fabsf(cs); }
    for (int i = 0; i < Isz; i++) { float cs = g_scs[i*Hsz + h]; nc += cs; dc += fabsf(cs); }
    float gl  = sp(gleak[h]);
    float cmt = sp(cm[h]) * (float)UNF;
    g_numconst[h] = gl * vleak[h] + nc;
    g_denconst[h] = cmt + gl + 1e-8f + dc;
    g_cmt[h] = cmt;
    for (int k = 0; k < Hsz; k++) {
        g_pwF[k*Hsz + h] = phase_W[h*Hsz + k];
        g_saF[k*Hsz + h] = sa_W[h*Hsz + k];
    }
}

// ---------------- kernel B: sensory pre-pass ----------------
__global__ __launch_bounds__(512, 1) void sens_kernel(const float* __restrict__ x)
{
    extern __shared__ float sm[];
    float2* sab = (float2*)sm;
    float*  xs  = sm + 2*Isz*Hsz;
    float*  pn  = xs + 128;
    float*  pd  = pn + 512;

    int tid = threadIdx.x;
    int h = tid & 127, g = tid >> 7;

    for (int r = tid; r < Isz*Hsz; r += 512) sab[r] = g_sab[r];

    float scs[32];
    #pragma unroll
    for (int il = 0; il < 32; il++) scs[il] = g_scs[(g*32 + il)*Hsz + h];

    float ncst = g_numconst[h], dcst = g_denconst[h];
    int s = blockIdx.x;

    for (int bb = 0; bb < 16; bb++) {
        int b = blockIdx.y * 16 + bb;
        __syncthreads();
        if (tid < Isz) xs[h] = x[(b*Ssz + s)*Isz + h];
        __syncthreads();
        float n = 0.f, d = 0.f;
        #pragma unroll
        for (int q = 0; q < 8; q++) {
            float4 x4 = *(const float4*)(xs + g*32 + 4*q);
            float xv[4] = {x4.x, x4.y, x4.z, x4.w};
            #pragma unroll
            for (int e = 0; e < 4; e++) {
                int il = 4*q + e;
                float2 p = sab[(g*32 + il)*Hsz + h];
                float t = tanhap(fmaf(p.x, xv[e], p.y));
                n = fmaf(scs[il], t, n);
                d = fmaf(fabsb(scs[il]), t, d);
            }
        }
        pn[g*Hsz + h] = n; pd[g*Hsz + h] = d;
        __syncthreads();
        if (g == 0) {
            float num = ncst + pn[h] + pn[Hsz + h] + pn[2*Hsz + h] + pn[3*Hsz + h];
            float den = dcst + pd[h] + pd[Hsz + h] + pd[2*Hsz + h] + pd[3*Hsz + h];
            int o = (b*Ssz + s)*Hsz + h;
            g_numbase[o] = num;
            g_denbase[o] = den;
        }
    }
}

// ---------------- smem byte offsets for seq kernel ----------------
#define OFF_PWF2   0                      // 128*129*4 = 66048
#define OFF_SAF2   66048                  // + 66048 = 132096
#define OFF_VFULL  132096                 // 2 slots * 128 * 4 = 1024
#define OFF_VFIN   133120                 // 128*4 = 512
#define OFF_PPH    133632                 // 4*128*4 = 2048
#define OFF_PSA    135680                 // 2048
#define OFF_SGB    137728                 // 512
#define OFF_MBAR   138240                 // 16
#define SMEM_SEQ   138368

// ---------------- kernel C: 2-CTA cluster, bulk-copy exchange, redundant epilogue ----------------
__global__ __launch_bounds__(SEQ_TPB, 1) __cluster_dims__(2, 1, 1)
void seq_kernel(const float* __restrict__ h0, const float* __restrict__ amplitude,
                const float* __restrict__ omega, const float* __restrict__ phase_b,
                const float* __restrict__ alpha_p, const float* __restrict__ beta_p,
                float* __restrict__ out, int write_hfinal)
{
    extern __shared__ char smc[];
    float* pwf2  = (float*)(smc + OFF_PWF2);    // [128][129] full columns
    float* saf2  = (float*)(smc + OFF_SAF2);    // [128][129]
    float* vfull = (float*)(smc + OFF_VFULL);   // [2][128] exchange slots
    float* vfin  = (float*)(smc + OFF_VFIN);    // [128] step-final state (local only)
    float* pph   = (float*)(smc + OFF_PPH);     // [4][128]
    float* psa   = (float*)(smc + OFF_PSA);     // [4][128]
    float* sgb   = (float*)(smc + OFF_SGB);     // [128]

    uint32_t sbase = smem_u32(smc);
    uint32_t mbar  = sbase + OFF_MBAR;

    uint32_t rank; asm("mov.u32 %0, %%cluster_ctarank;" : "=r"(rank));
    uint32_t peerR = rank ^ 1u;
    int b = blockIdx.x >> 1;
    int own_base  = (int)rank * HHALF;
    int peer_base = (int)peerR * HHALF;

    int tid  = threadIdx.x;
    int lane = tid & 31;
    int warp = tid >> 5;
    int g    = lane & 7;                      // src subgroup 0..7 (unfold layout)
    int hl   = (warp << 2) | (lane >> 3);     // 0..63 local dst
    int habs = own_base + hl;
    int h2   = tid & 127;                     // epilogue layout: dst
    int g2   = tid >> 7;                      // epilogue layout: k quarter

    // preload FULL epilogue weight matrices (stride 129 -> conflict-free)
    for (int idx = tid; idx < Hsz*Hsz; idx += SEQ_TPB) {
        int k = idx >> 7, hh = idx & 127;
        pwf2[k*129 + hh] = g_pwF[idx];
        saf2[k*129 + hh] = g_saF[idx];
    }

    // per-thread edge params in registers: srcs j = base + jl*8 + g
    float ao[8], bo[8], cso[8], ap[8], bp[8], csp[8];
    #pragma unroll
    for (int jl = 0; jl < 8; jl++) {
        int jo = own_base  + jl*8 + g;
        int jp = peer_base + jl*8 + g;
        float2 r0 = g_rab[jo*Hsz + habs];
        float2 r1 = g_rab[jp*Hsz + habs];
        ao[jl] = r0.x; bo[jl] = r0.y; cso[jl] = g_rcs[jo*Hsz + habs];
        ap[jl] = r1.x; bp[jl] = r1.y; csp[jl] = g_rcs[jp*Hsz + habs];
    }
    float cmt = g_cmt[habs];
    float aa2 = alpha_p[0] * amplitude[h2];
    float om2 = omega[h2];
    float pb2 = phase_b[h2];
    float bet = beta_p[0];

    if (tid < Hsz) vfin[tid] = h0[b*Hsz + tid];   // full initial state, no exchange
    if (tid == 0) mbar_init(mbar, 1);             // 1 arrive (the expect_tx) per phase
    __syncthreads();
    asm volatile("barrier.cluster.arrive.aligned;" ::: "memory");
    asm volatile("barrier.cluster.wait.aligned;"   ::: "memory");

    uint32_t vfull_rm, mbar_rm;
    asm("mapa.shared::cluster.u32 %0, %1, %2;" : "=r"(vfull_rm) : "r"(sbase + OFF_VFULL), "r"(peerR));
    asm("mapa.shared::cluster.u32 %0, %1, %2;" : "=r"(mbar_rm)  : "r"(sbase + OFF_MBAR),  "r"(peerR));

    if (tid == 0) mbar_expect_tx(mbar, 256);      // receive #0

    uint32_t rc = 0;
    float nb = g_numbase[(b*Ssz)*Hsz + habs];
    float db = g_denbase[(b*Ssz)*Hsz + habs];
    float v;

    for (int s = 0; s < Ssz; s++) {
        float nb_n = 0.f, db_n = 0.f;
        if (s + 1 < Ssz) {
            nb_n = g_numbase[(b*Ssz + s + 1)*Hsz + habs];
            db_n = g_denbase[(b*Ssz + s + 1)*Hsz + habs];
        }

        // ---- unfold 0: fully local (vfin holds full previous state) ----
        v = vfin[habs];
        {
            float n = 0.f, d = 0.f;
            #pragma unroll
            for (int jl = 0; jl < 8; jl++) {
                float t = tanhap(fmaf(ao[jl], vfin[own_base + jl*8 + g], bo[jl]));
                n = fmaf(cso[jl], t, n);
                d = fmaf(fabsb(cso[jl]), t, d);
            }
            #pragma unroll
            for (int jl = 0; jl < 8; jl++) {
                float t = tanhap(fmaf(ap[jl], vfin[peer_base + jl*8 + g], bp[jl]));
                n = fmaf(csp[jl], t, n);
                d = fmaf(fabsb(csp[jl]), t, d);
            }
            n += __shfl_xor_sync(0xffffffffu, n, 1);
            n += __shfl_xor_sync(0xffffffffu, n, 2);
            n += __shfl_xor_sync(0xffffffffu, n, 4);
            d += __shfl_xor_sync(0xffffffffu, d, 1);
            d += __shfl_xor_sync(0xffffffffu, d, 2);
            d += __shfl_xor_sync(0xffffffffu, d, 4);
            v = __fdividef(fmaf(cmt, v, nb + n), db + d);
        }
        if (g == 0) vfull[0*Hsz + habs] = v;     // slot 0
        __syncthreads();
        if (tid == 0)
            bulk_to_peer(vfull_rm + 0*512u + (uint32_t)own_base*4u,
                         sbase + OFF_VFULL + 0*512u + (uint32_t)own_base*4u, 256u, mbar_rm);

        // ---- unfolds 1..5 ----
        #pragma unroll 1
        for (int u = 1; u < UNF; u++) {
            int rslot = (u - 1) & 1;
            int wslot = u & 1;
            const float* vf = vfull + rslot*Hsz;
            float n = 0.f, d = 0.f;
            // own half (local write, visible via syncthreads)
            #pragma unroll
            for (int jl = 0; jl < 8; jl++) {
                float t = tanhap(fmaf(ao[jl], vf[own_base + jl*8 + g], bo[jl]));
                n = fmaf(cso[jl], t, n);
                d = fmaf(fabsb(cso[jl]), t, d);
            }
            // receive peer half
            mbar_wait_cluster(mbar, rc & 1u); rc++;
            if (tid == 0) mbar_expect_tx(mbar, 256);   // pipeline next phase
            #pragma unroll
            for (int jl = 0; jl < 8; jl++) {
                float t = tanhap(fmaf(ap[jl], vf[peer_base + jl*8 + g], bp[jl]));
                n = fmaf(csp[jl], t, n);
                d = fmaf(fabsb(csp[jl]), t, d);
            }
            n += __shfl_xor_sync(0xffffffffu, n, 1);
            n += __shfl_xor_sync(0xffffffffu, n, 2);
            n += __shfl_xor_sync(0xffffffffu, n, 4);
            d += __shfl_xor_sync(0xffffffffu, d, 1);
            d += __shfl_xor_sync(0xffffffffu, d, 2);
            d += __shfl_xor_sync(0xffffffffu, d, 4);
            v = __fdividef(fmaf(cmt, v, nb + n), db + d);
            if (g == 0) vfull[wslot*Hsz + habs] = v;
            __syncthreads();
            if (tid == 0)
                bulk_to_peer(vfull_rm + (uint32_t)wslot*512u + (uint32_t)own_base*4u,
                             sbase + OFF_VFULL + (uint32_t)wslot*512u + (uint32_t)own_base*4u,
                             256u, mbar_rm);
        }

        // ---- epilogue: wait final half, then FULLY LOCAL redundant compute ----
        mbar_wait_cluster(mbar, rc & 1u); rc++;
        if (tid == 0) mbar_expect_tx(mbar, 256);       // next step's first receive
        const float* v6 = vfull + 1*Hsz;               // slot written at u=5 (5&1=1)

        // phi partials over k-quarter g2
        {
            float php = 0.f;
            #pragma unroll 8
            for (int kl = 0; kl < 32; kl++) {
                int k = g2*32 + kl;
                php = fmaf(pwf2[k*129 + h2], v6[k], php);
            }
            pph[g2*Hsz + h2] = php;
        }
        __syncthreads();
        float phi = pph[h2] + pph[Hsz + h2] + pph[2*Hsz + h2] + pph[3*Hsz + h2] + pb2;
        float vp  = v6[h2] + aa2 * __sinf(fmaf(om2, (float)s, phi));
        if (g2 == 0) sgb[h2] = fmaf(0.5f, tanhap(0.5f * vp), 0.5f);
        __syncthreads();
        {
            float accp = 0.f;
            #pragma unroll 8
            for (int kl = 0; kl < 32; kl++) {
                int k = g2*32 + kl;
                accp = fmaf(saf2[k*129 + h2], sgb[k], accp);
            }
            psa[g2*Hsz + h2] = accp;
        }
        __syncthreads();
        if (g2 == 0) {
            float acc = psa[h2] + psa[Hsz + h2] + psa[2*Hsz + h2] + psa[3*Hsz + h2];
            float vfl = fmaf(bet, acc, vp);
            out[(b*Ssz + s)*Hsz + h2] = vfl;
            vfin[h2] = vfl;
        }
        __syncthreads();

        nb = nb_n; db = db_n;
    }

    if (write_hfinal && g2 == 0)
        out[Bsz*Ssz*Hsz + b*Hsz + h2] = vfin[h2];

    asm volatile("barrier.cluster.arrive.aligned;" ::: "memory");
    asm volatile("barrier.cluster.wait.aligned;"   ::: "memory");
}

// ---------------- launch ----------------
extern "C" void kernel_launch(void* const* d_in, const int* in_sizes, int n_in,
                              void* d_out, int out_size)
{
    const float* x        = (const float*)d_in[0];
    const float* h0       = (const float*)d_in[1];
    const float* input_w  = (const float*)d_in[2];
    const float* input_b  = (const float*)d_in[3];
    const float* gleak    = (const float*)d_in[4];
    const float* vleak    = (const float*)d_in[5];
    const float* cm       = (const float*)d_in[6];
    const float* sigma    = (const float*)d_in[7];
    const float* mu       = (const float*)d_in[8];
    const float* w        = (const float*)d_in[9];
    const float* erev     = (const float*)d_in[10];
    const float* s_sigma  = (const float*)d_in[11];
    const float* s_mu     = (const float*)d_in[12];
    const float* s_w      = (const float*)d_in[13];
    const float* s_erev   = (const float*)d_in[14];
    const float* amplitude= (const float*)d_in[15];
    const float* omega    = (const float*)d_in[16];
    const float* phase_W  = (const float*)d_in[17];
    const float* phase_b  = (const float*)d_in[18];
    const float* alpha    = (const float*)d_in[19];
    const float* sa_W     = (const float*)d_in[20];
    const float* beta     = (const float*)d_in[21];
    float* out = (float*)d_out;

    const int smem_sens = 2*Isz*Hsz*4 + (128 + 512 + 512)*4;
    cudaFuncSetAttribute(sens_kernel, cudaFuncAttributeMaxDynamicSharedMemorySize, smem_sens);
    cudaFuncSetAttribute(seq_kernel,  cudaFuncAttributeMaxDynamicSharedMemorySize, SMEM_SEQ);

    prep_kernel<<<Hsz + Isz, Hsz>>>(sigma, mu, w, erev, s_sigma, s_mu, s_w, s_erev, input_w, input_b);
    prep2_kernel<<<1, Hsz>>>(gleak, vleak, cm, phase_W, sa_W);

    dim3 gb(Ssz, Bsz/16);
    sens_kernel<<<gb, 512, smem_sens>>>(x);

    int whf = (out_size >= Bsz*Ssz*Hsz + Bsz*Hsz) ? 1 : 0;
    seq_kernel<<<Bsz*2, SEQ_TPB, SMEM_SEQ>>>(h0, amplitude, omega, phase_b, alpha, beta, out, whf);
}

// round 7
// speedup vs baseline: 2.3671x; 1.0256x over previous
#include <cuda_runtime.h>
#include <cuda_bf16.h>
#include <cstdint>

#define Bsz 64
#define Ssz 256
#define Isz 128
#define Hsz 128
#define UNF 6

#define SEQ_TPB 512
#define HHALF 64

// ---------------- device scratch ----------------
__device__ float2 g_rab[Hsz*Hsz];       // (a,b): a=0.5*sigma, b=-0.5*sigma*mu, [src][dst]
__device__ float  g_rcs[Hsz*Hsz];       // 0.5*softplus(w)*erev, [src][dst]
__device__ float2 g_sab[Isz*Hsz];
__device__ float  g_scs[Isz*Hsz];
__device__ float  g_numconst[Hsz];
__device__ float  g_denconst[Hsz];
__device__ float  g_cmt[Hsz];
__device__ uint32_t g_pwB[(Hsz/2)*Hsz]; // phase_W bf16x2 packed: [k2][h], lo=k=2*k2, hi=k=2*k2+1
__device__ uint32_t g_saB[(Hsz/2)*Hsz]; // sa_W    bf16x2 packed: [k2][h]
__device__ float  g_numbase[Bsz*Ssz*Hsz];
__device__ float  g_denbase[Bsz*Ssz*Hsz];

// ---------------- helpers ----------------
__device__ __forceinline__ float sp(float x) { return log1pf(expf(x)); }
__device__ __forceinline__ float tanhap(float x) {
    float y; asm("tanh.approx.f32 %0, %1;" : "=f"(y) : "f"(x)); return y;
}
__device__ __forceinline__ float fabsb(float x) {
    return __int_as_float(__float_as_int(x) & 0x7fffffff);
}
__device__ __forceinline__ float2 bf2f2(uint32_t u) {
    return __bfloat1622float2(*reinterpret_cast<__nv_bfloat162*>(&u));
}
__device__ __forceinline__ uint32_t smem_u32(const void* p) {
    uint32_t a; asm("{ .reg .u64 t; cvta.to.shared.u64 t, %1; cvt.u32.u64 %0, t; }" : "=r"(a) : "l"(p));
    return a;
}
__device__ __forceinline__ void mbar_init(uint32_t mbar, uint32_t cnt) {
    asm volatile("mbarrier.init.shared.b64 [%0], %1;" :: "r"(mbar), "r"(cnt) : "memory");
}
__device__ __forceinline__ void mbar_expect_tx(uint32_t mbar, uint32_t bytes) {
    asm volatile("mbarrier.arrive.expect_tx.shared.b64 _, [%0], %1;" :: "r"(mbar), "r"(bytes) : "memory");
}
__device__ __forceinline__ void mbar_wait_cluster(uint32_t mbar, uint32_t par) {
    asm volatile(
        "{\n\t.reg .pred P;\n"
        "WL_%=:\n\t"
        "mbarrier.try_wait.parity.acquire.cluster.shared::cta.b64 P, [%0], %1, 0x989680;\n\t"
        "@!P bra WL_%=;\n\t}"
        :: "r"(mbar), "r"(par) : "memory");
}
// one-shot 256B push of our v-half into the peer's buffer; HW complete_tx on peer mbar
__device__ __forceinline__ void bulk_to_peer(uint32_t dst_cluster, uint32_t src_cta,
                                             uint32_t bytes, uint32_t mbar_cluster) {
    asm volatile("fence.proxy.async.shared::cta;" ::: "memory");
    asm volatile("cp.async.bulk.shared::cluster.shared::cta.mbarrier::complete_tx::bytes "
                 "[%0], [%1], %2, [%3];"
                 :: "r"(dst_cluster), "r"(src_cta), "r"(bytes), "r"(mbar_cluster) : "memory");
}

// ---------------- kernel A: per-edge param folding ----------------
__global__ void prep_kernel(const float* __restrict__ sigma, const float* __restrict__ mu,
                            const float* __restrict__ w,     const float* __restrict__ erev,
                            const float* __restrict__ s_sigma, const float* __restrict__ s_mu,
                            const float* __restrict__ s_w,   const float* __restrict__ s_erev,
                            const float* __restrict__ input_w, const float* __restrict__ input_b)
{
    int r = blockIdx.x, h = threadIdx.x;
    if (r < Hsz) {
        int idx = r*Hsz + h;
        float a = 0.5f * sigma[idx];
        g_rab[idx] = make_float2(a, -a * mu[idx]);
        g_rcs[idx] = 0.5f * sp(w[idx]) * erev[idx];
    } else {
        int i = r - Hsz;
        int idx = i*Hsz + h;
        float a = 0.5f * s_sigma[idx];
        g_sab[idx] = make_float2(a * input_w[i], a * (input_b[i] - s_mu[idx]));
        g_scs[idx] = 0.5f * sp(s_w[idx]) * s_erev[idx];
    }
}

// ---------------- kernel A2: per-h constants + packed bf16x2 epilogue weights ----------------
__global__ void prep2_kernel(const float* __restrict__ gleak, const float* __restrict__ vleak,
                             const float* __restrict__ cm,
                             const float* __restrict__ phase_W, const float* __restrict__ sa_W)
{
    int h = threadIdx.x;
    float nc = 0.f, dc = 0.f;
    for (int j = 0; j < Hsz; j++) { float cs = g_rcs[j*Hsz + h]; nc += cs; dc += fabsf(cs); }
    for (int i = 0; i < Isz; i++) { float cs = g_scs[i*Hsz + h]; nc += cs; dc += fabsf(cs); }
    float gl  = sp(gleak[h]);
    float cmt = sp(cm[h]) * (float)UNF;
    g_numconst[h] = gl * vleak[h] + nc;
    g_denconst[h] = cmt + gl + 1e-8f + dc;
    g_cmt[h] = cmt;
    for (int k2 = 0; k2 < Hsz/2; k2++) {
        __nv_bfloat162 p, q;
        p.x = __float2bfloat16(phase_W[h*Hsz + 2*k2]);      // lo = even k
        p.y = __float2bfloat16(phase_W[h*Hsz + 2*k2 + 1]);  // hi = odd k
        q.x = __float2bfloat16(sa_W[h*Hsz + 2*k2]);
        q.y = __float2bfloat16(sa_W[h*Hsz + 2*k2 + 1]);
        g_pwB[k2*Hsz + h] = *reinterpret_cast<uint32_t*>(&p);
        g_saB[k2*Hsz + h] = *reinterpret_cast<uint32_t*>(&q);
    }
}

// ---------------- kernel B: sensory pre-pass ----------------
__global__ __launch_bounds__(512, 1) void sens_kernel(const float* __restrict__ x)
{
    extern __shared__ float sm[];
    float2* sab = (float2*)sm;
    float*  xs  = sm + 2*Isz*Hsz;
    float*  pn  = xs + 128;
    float*  pd  = pn + 512;

    int tid = threadIdx.x;
    int h = tid & 127, g = tid >> 7;

    for (int r = tid; r < Isz*Hsz; r += 512) sab[r] = g_sab[r];

    float scs[32];
    #pragma unroll
    for (int il = 0; il < 32; il++) scs[il] = g_scs[(g*32 + il)*Hsz + h];

    float ncst = g_numconst[h], dcst = g_denconst[h];
    int s = blockIdx.x;

    for (int bb = 0; bb < 16; bb++) {
        int b = blockIdx.y * 16 + bb;
        __syncthreads();
        if (tid < Isz) xs[h] = x[(b*Ssz + s)*Isz + h];
        __syncthreads();
        float n = 0.f, d = 0.f;
        #pragma unroll
        for (int q = 0; q < 8; q++) {
            float4 x4 = *(const float4*)(xs + g*32 + 4*q);
            float xv[4] = {x4.x, x4.y, x4.z, x4.w};
            #pragma unroll
            for (int e = 0; e < 4; e++) {
                int il = 4*q + e;
                float2 p = sab[(g*32 + il)*Hsz + h];
                float t = tanhap(fmaf(p.x, xv[e], p.y));
                n = fmaf(scs[il], t, n);
                d = fmaf(fabsb(scs[il]), t, d);
            }
        }
        pn[g*Hsz + h] = n; pd[g*Hsz + h] = d;
        __syncthreads();
        if (g == 0) {
            float num = ncst + pn[h] + pn[Hsz + h] + pn[2*Hsz + h] + pn[3*Hsz + h];
            float den = dcst + pd[h] + pd[Hsz + h] + pd[2*Hsz + h] + pd[3*Hsz + h];
            int o = (b*Ssz + s)*Hsz + h;
            g_numbase[o] = num;
            g_denbase[o] = den;
        }
    }
}

// ---------------- smem byte offsets for seq kernel ----------------
#define OFF_PWB    0                      // 64*128*4 = 32768
#define OFF_SAB    32768                  // + 32768 = 65536
#define OFF_VFULL  65536                  // 2 slots * 128 * 4 = 1024
#define OFF_VFIN   66560                  // 512
#define OFF_PPH    67072                  // 4*128*4 = 2048
#define OFF_PSA    69120                  // 2048
#define OFF_SGB    71168                  // 512
#define OFF_MBAR   71680                  // 16
#define SMEM_SEQ   71936

// ---------------- kernel C: 2-CTA cluster, bulk-copy exchange, bf16 redundant epilogue ----------------
__global__ __launch_bounds__(SEQ_TPB, 1) __cluster_dims__(2, 1, 1)
void seq_kernel(const float* __restrict__ h0, const float* __restrict__ amplitude,
                const float* __restrict__ omega, const float* __restrict__ phase_b,
                const float* __restrict__ alpha_p, const float* __restrict__ beta_p,
                float* __restrict__ out, int write_hfinal)
{
    extern __shared__ char smc[];
    uint32_t* pwb = (uint32_t*)(smc + OFF_PWB);   // [64][128] bf16x2
    uint32_t* sab = (uint32_t*)(smc + OFF_SAB);   // [64][128] bf16x2
    float* vfull  = (float*)(smc + OFF_VFULL);    // [2][128] exchange slots
    float* vfin   = (float*)(smc + OFF_VFIN);     // [128] step-final state (local only)
    float* pph    = (float*)(smc + OFF_PPH);      // [4][128]
    float* psa    = (float*)(smc + OFF_PSA);      // [4][128]
    float* sgb    = (float*)(smc + OFF_SGB);      // [128]

    uint32_t sbase = smem_u32(smc);
    uint32_t mbar  = sbase + OFF_MBAR;

    uint32_t rank; asm("mov.u32 %0, %%cluster_ctarank;" : "=r"(rank));
    uint32_t peerR = rank ^ 1u;
    int b = blockIdx.x >> 1;
    int own_base  = (int)rank * HHALF;
    int peer_base = (int)peerR * HHALF;

    int tid  = threadIdx.x;
    int lane = tid & 31;
    int warp = tid >> 5;
    int g    = lane & 7;                      // src subgroup 0..7 (unfold layout)
    int hl   = (warp << 2) | (lane >> 3);     // 0..63 local dst
    int habs = own_base + hl;
    int h2   = tid & 127;                     // epilogue layout: dst
    int g2   = tid >> 7;                      // epilogue layout: k quarter

    // preload packed epilogue weights: [k2][h] u32, conflict-free rows
    for (int idx = tid; idx < (Hsz/2)*Hsz; idx += SEQ_TPB) {
        pwb[idx] = g_pwB[idx];
        sab[idx] = g_saB[idx];
    }

    // per-thread edge params in registers: srcs j = base + jl*8 + g
    float ao[8], bo[8], cso[8], ap[8], bp[8], csp[8];
    #pragma unroll
    for (int jl = 0; jl < 8; jl++) {
        int jo = own_base  + jl*8 + g;
        int jp = peer_base + jl*8 + g;
        float2 r0 = g_rab[jo*Hsz + habs];
        float2 r1 = g_rab[jp*Hsz + habs];
        ao[jl] = r0.x; bo[jl] = r0.y; cso[jl] = g_rcs[jo*Hsz + habs];
        ap[jl] = r1.x; bp[jl] = r1.y; csp[jl] = g_rcs[jp*Hsz + habs];
    }
    float cmt = g_cmt[habs];
    float aa2 = alpha_p[0] * amplitude[h2];
    float om2 = omega[h2];
    float pb2 = phase_b[h2];
    float bet = beta_p[0];

    if (tid < Hsz) vfin[tid] = h0[b*Hsz + tid];   // full initial state, no exchange
    if (tid == 0) mbar_init(mbar, 1);             // 1 arrive (the expect_tx) per phase
    __syncthreads();
    asm volatile("barrier.cluster.arrive.aligned;" ::: "memory");
    asm volatile("barrier.cluster.wait.aligned;"   ::: "memory");

    uint32_t vfull_rm, mbar_rm;
    asm("mapa.shared::cluster.u32 %0, %1, %2;" : "=r"(vfull_rm) : "r"(sbase + OFF_VFULL), "r"(peerR));
    asm("mapa.shared::cluster.u32 %0, %1, %2;" : "=r"(mbar_rm)  : "r"(sbase + OFF_MBAR),  "r"(peerR));

    if (tid == 0) mbar_expect_tx(mbar, 256);      // receive #0

    uint32_t rc = 0;
    float nb = g_numbase[(b*Ssz)*Hsz + habs];
    float db = g_denbase[(b*Ssz)*Hsz + habs];
    float v;

    for (int s = 0; s < Ssz; s++) {
        float nb_n = 0.f, db_n = 0.f;
        if (s + 1 < Ssz) {
            nb_n = g_numbase[(b*Ssz + s + 1)*Hsz + habs];
            db_n = g_denbase[(b*Ssz + s + 1)*Hsz + habs];
        }

        // ---- unfold 0: fully local (vfin holds full previous state) ----
        v = vfin[habs];
        {
            float n = 0.f, d = 0.f;
            #pragma unroll
            for (int jl = 0; jl < 8; jl++) {
                float t = tanhap(fmaf(ao[jl], vfin[own_base + jl*8 + g], bo[jl]));
                n = fmaf(cso[jl], t, n);
                d = fmaf(fabsb(cso[jl]), t, d);
            }
            #pragma unroll
            for (int jl = 0; jl < 8; jl++) {
                float t = tanhap(fmaf(ap[jl], vfin[peer_base + jl*8 + g], bp[jl]));
                n = fmaf(csp[jl], t, n);
                d = fmaf(fabsb(csp[jl]), t, d);
            }
            n += __shfl_xor_sync(0xffffffffu, n, 1);
            n += __shfl_xor_sync(0xffffffffu, n, 2);
            n += __shfl_xor_sync(0xffffffffu, n, 4);
            d += __shfl_xor_sync(0xffffffffu, d, 1);
            d += __shfl_xor_sync(0xffffffffu, d, 2);
            d += __shfl_xor_sync(0xffffffffu, d, 4);
            v = __fdividef(fmaf(cmt, v, nb + n), db + d);
        }
        if (g == 0) vfull[0*Hsz + habs] = v;     // slot 0
        __syncthreads();
        if (tid == 0)
            bulk_to_peer(vfull_rm + 0*512u + (uint32_t)own_base*4u,
                         sbase + OFF_VFULL + 0*512u + (uint32_t)own_base*4u, 256u, mbar_rm);

        // ---- unfolds 1..5 ----
        #pragma unroll 1
        for (int u = 1; u < UNF; u++) {
            int rslot = (u - 1) & 1;
            int wslot = u & 1;
            const float* vf = vfull + rslot*Hsz;
            float n = 0.f, d = 0.f;
            // own half (local write, visible via syncthreads)
            #pragma unroll
            for (int jl = 0; jl < 8; jl++) {
                float t = tanhap(fmaf(ao[jl], vf[own_base + jl*8 + g], bo[jl]));
                n = fmaf(cso[jl], t, n);
                d = fmaf(fabsb(cso[jl]), t, d);
            }
            // receive peer half
            mbar_wait_cluster(mbar, rc & 1u); rc++;
            if (tid == 0) mbar_expect_tx(mbar, 256);   // pipeline next phase
            #pragma unroll
            for (int jl = 0; jl < 8; jl++) {
                float t = tanhap(fmaf(ap[jl], vf[peer_base + jl*8 + g], bp[jl]));
                n = fmaf(csp[jl], t, n);
                d = fmaf(fabsb(csp[jl]), t, d);
            }
            n += __shfl_xor_sync(0xffffffffu, n, 1);
            n += __shfl_xor_sync(0xffffffffu, n, 2);
            n += __shfl_xor_sync(0xffffffffu, n, 4);
            d += __shfl_xor_sync(0xffffffffu, d, 1);
            d += __shfl_xor_sync(0xffffffffu, d, 2);
            d += __shfl_xor_sync(0xffffffffu, d, 4);
            v = __fdividef(fmaf(cmt, v, nb + n), db + d);
            if (g == 0) vfull[wslot*Hsz + habs] = v;
            __syncthreads();
            if (tid == 0)
                bulk_to_peer(vfull_rm + (uint32_t)wslot*512u + (uint32_t)own_base*4u,
                             sbase + OFF_VFULL + (uint32_t)wslot*512u + (uint32_t)own_base*4u,
                             256u, mbar_rm);
        }

        // ---- epilogue: wait final half, then FULLY LOCAL redundant compute (bf16 weights) ----
        mbar_wait_cluster(mbar, rc & 1u); rc++;
        if (tid == 0) mbar_expect_tx(mbar, 256);       // next step's first receive
        const float* v6 = vfull + 1*Hsz;               // slot written at u=5 (5&1=1)
        const float2* v6f2 = (const float2*)v6;

        // phi partials over k-quarter g2 (16 k2-pairs each)
        {
            float php = 0.f;
            #pragma unroll 8
            for (int i = 0; i < 16; i++) {
                int k2 = g2*16 + i;
                float2 wv = bf2f2(pwb[k2*Hsz + h2]);
                float2 v2 = v6f2[k2];
                php = fmaf(wv.x, v2.x, fmaf(wv.y, v2.y, php));
            }
            pph[g2*Hsz + h2] = php;
        }
        __syncthreads();
        float phi = pph[h2] + pph[Hsz + h2] + pph[2*Hsz + h2] + pph[3*Hsz + h2] + pb2;
        float vp  = v6[h2] + aa2 * __sinf(fmaf(om2, (float)s, phi));
        if (g2 == 0) sgb[h2] = fmaf(0.5f, tanhap(0.5f * vp), 0.5f);
        __syncthreads();
        {
            const float2* sgf2 = (const float2*)sgb;
            float accp = 0.f;
            #pragma unroll 8
            for (int i = 0; i < 16; i++) {
                int k2 = g2*16 + i;
                float2 wv = bf2f2(sab[k2*Hsz + h2]);
                float2 s2 = sgf2[k2];
                accp = fmaf(wv.x, s2.x, fmaf(wv.y, s2.y, accp));
            }
            psa[g2*Hsz + h2] = accp;
        }
        __syncthreads();
        if (g2 == 0) {
            float acc = psa[h2] + psa[Hsz + h2] + psa[2*Hsz + h2] + psa[3*Hsz + h2];
            float vfl = fmaf(bet, acc, vp);
            out[(b*Ssz + s)*Hsz + h2] = vfl;
            vfin[h2] = vfl;
        }
        __syncthreads();

        nb = nb_n; db = db_n;
    }

    if (write_hfinal && g2 == 0)
        out[Bsz*Ssz*Hsz + b*Hsz + h2] = vfin[h2];

    asm volatile("barrier.cluster.arrive.aligned;" ::: "memory");
    asm volatile("barrier.cluster.wait.aligned;"   ::: "memory");
}

// ---------------- launch ----------------
extern "C" void kernel_launch(void* const* d_in, const int* in_sizes, int n_in,
                              void* d_out, int out_size)
{
    const float* x        = (const float*)d_in[0];
    const float* h0       = (const float*)d_in[1];
    const float* input_w  = (const float*)d_in[2];
    const float* input_b  = (const float*)d_in[3];
    const float* gleak    = (const float*)d_in[4];
    const float* vleak    = (const float*)d_in[5];
    const float* cm       = (const float*)d_in[6];
    const float* sigma    = (const float*)d_in[7];
    const float* mu       = (const float*)d_in[8];
    const float* w        = (const float*)d_in[9];
    const float* erev     = (const float*)d_in[10];
    const float* s_sigma  = (const float*)d_in[11];
    const float* s_mu     = (const float*)d_in[12];
    const float* s_w      = (const float*)d_in[13];
    const float* s_erev   = (const float*)d_in[14];
    const float* amplitude= (const float*)d_in[15];
    const float* omega    = (const float*)d_in[16];
    const float* phase_W  = (const float*)d_in[17];
    const float* phase_b  = (const float*)d_in[18];
    const float* alpha    = (const float*)d_in[19];
    const float* sa_W     = (const float*)d_in[20];
    const float* beta     = (const float*)d_in[21];
    float* out = (float*)d_out;

    const int smem_sens = 2*Isz*Hsz*4 + (128 + 512 + 512)*4;
    cudaFuncSetAttribute(sens_kernel, cudaFuncAttributeMaxDynamicSharedMemorySize, smem_sens);
    cudaFuncSetAttribute(seq_kernel,  cudaFuncAttributeMaxDynamicSharedMemorySize, SMEM_SEQ);

    prep_kernel<<<Hsz + Isz, Hsz>>>(sigma, mu, w, erev, s_sigma, s_mu, s_w, s_erev, input_w, input_b);
    prep2_kernel<<<1, Hsz>>>(gleak, vleak, cm, phase_W, sa_W);

    dim3 gb(Ssz, Bsz/16);
    sens_kernel<<<gb, 512, smem_sens>>>(x);

    int whf = (out_size >= Bsz*Ssz*Hsz + Bsz*Hsz) ? 1 : 0;
    seq_kernel<<<Bsz*2, SEQ_TPB, SMEM_SEQ>>>(h0, amplitude, omega, phase_b, alpha, beta, out, whf);
}